// round 2
// baseline (speedup 1.0000x reference)
#include <cuda_runtime.h>
#include <math.h>

#define B_TOK   1024
#define D_DIM   1024
#define H_DIM   2048
#define O_DIM   1024
#define E_NUM   8
#define MAXPAIR 2048            // B * TOP_K
#define TILE_M  128
#define MAXROWS 3072            // 2048 + 8*128 padding slack
#define MAXTILES 24

// ---------------- scratch (static device globals: allocation-free) ----------
__device__ float d_h1[MAXROWS * H_DIM];
__device__ float d_h2[MAXROWS * H_DIM];
__device__ int   d_rowtok[MAXROWS];
__device__ float d_rowgate[MAXROWS];
__device__ int   d_counts[E_NUM];
__device__ int   d_fill[E_NUM];
__device__ int   d_tileExpert[MAXTILES];
__device__ int   d_tileRowBase[MAXTILES];
__device__ int   d_pairEid[MAXPAIR];
__device__ float d_pairGate[MAXPAIR];

// ---------------- init: reset counters + padded-row map ---------------------
__global__ void init_kernel() {
    int t = blockIdx.x * blockDim.x + threadIdx.x;
    if (t < E_NUM) d_counts[t] = 0;
    for (int i = t; i < MAXROWS; i += gridDim.x * blockDim.x) {
        d_rowtok[i]  = -1;
        d_rowgate[i] = 0.0f;
    }
}

// ---------------- router: logits -> softmax -> top2 -> renorm gates ---------
__global__ void router_kernel(const float* __restrict__ x,
                              const float* __restrict__ Wr,
                              const float* __restrict__ br) {
    __shared__ float xs[D_DIM];
    __shared__ float lg[E_NUM];
    int b = blockIdx.x;
    const float* xr = x + (size_t)b * D_DIM;
    for (int i = threadIdx.x; i < D_DIM; i += 256) xs[i] = xr[i];
    __syncthreads();

    int warp = threadIdx.x >> 5, lane = threadIdx.x & 31;
    // warp e computes logit for expert e (E_NUM == 8 warps)
    float s = 0.0f;
    for (int d = lane; d < D_DIM; d += 32) s += xs[d] * Wr[d * E_NUM + warp];
    #pragma unroll
    for (int o = 16; o > 0; o >>= 1) s += __shfl_down_sync(0xffffffffu, s, o);
    if (lane == 0) lg[warp] = s + br[warp];
    __syncthreads();

    if (threadIdx.x == 0) {
        float m = lg[0];
        #pragma unroll
        for (int e = 1; e < E_NUM; e++) m = fmaxf(m, lg[e]);
        float p[E_NUM]; float sum = 0.0f;
        #pragma unroll
        for (int e = 0; e < E_NUM; e++) { p[e] = expf(lg[e] - m); sum += p[e]; }
        // top-2, ties -> lowest index (strict >) matching jax.lax.top_k
        int i0 = 0;
        #pragma unroll
        for (int e = 1; e < E_NUM; e++) if (p[e] > p[i0]) i0 = e;
        int i1 = (i0 == 0) ? 1 : 0;
        #pragma unroll
        for (int e = 0; e < E_NUM; e++) if (e != i0 && p[e] > p[i1]) i1 = e;
        float w0 = p[i0] / sum, w1 = p[i1] / sum;
        float den = w0 + w1 + 1e-6f;
        d_pairEid[b * 2 + 0] = i0;  d_pairGate[b * 2 + 0] = w0 / den;
        d_pairEid[b * 2 + 1] = i1;  d_pairGate[b * 2 + 1] = w1 / den;
        atomicAdd(&d_counts[i0], 1);
        atomicAdd(&d_counts[i1], 1);
    }
}

// ---------------- scan: padded segment offsets + tile->expert map -----------
__global__ void scan_kernel() {
    if (threadIdx.x != 0 || blockIdx.x != 0) return;
    int off = 0, rt = 0;
    for (int e = 0; e < E_NUM; e++) {
        int c  = d_counts[e];
        int pc = (c + TILE_M - 1) / TILE_M * TILE_M;
        d_fill[e] = off;
        for (int t = 0; t < pc / TILE_M; t++) {
            d_tileExpert[rt]  = e;
            d_tileRowBase[rt] = off + t * TILE_M;
            rt++;
        }
        off += pc;
    }
    for (; rt < MAXTILES; rt++) d_tileExpert[rt] = -1;
}

// ---------------- scatter pairs into padded per-expert segments -------------
__global__ void scatter_kernel() {
    int p = blockIdx.x * blockDim.x + threadIdx.x;
    if (p >= MAXPAIR) return;
    int e   = d_pairEid[p];
    int pos = atomicAdd(&d_fill[e], 1);
    d_rowtok[pos]  = p >> 1;          // token id
    d_rowgate[pos] = d_pairGate[p];
}

// ---------------- zero output -----------------------------------------------
__global__ void zero_out_kernel(float* __restrict__ out) {
    int n = B_TOK * O_DIM;
    for (int i = blockIdx.x * blockDim.x + threadIdx.x; i < n;
         i += gridDim.x * blockDim.x)
        out[i] = 0.0f;
}

// ---------------- grouped GEMM: 128x128 tile, 8x8 microtile, K-step 8 -------
// MODE 0: A = x gathered via d_rowtok, epilogue relu           -> C [row,N]
// MODE 1: A = h (padded rows, direct),  epilogue relu          -> C [row,N]
// MODE 2: A = h,  epilogue gate * atomicAdd scatter into out   -> C [tok,N]
template <int MODE>
__global__ __launch_bounds__(256, 2)
void moe_gemm_kernel(const float* __restrict__ A,
                     const float* __restrict__ Wall,
                     const float* __restrict__ Ball,
                     float* __restrict__ C,
                     int K, int N) {
    int rt = blockIdx.x;
    int e  = d_tileExpert[rt];
    if (e < 0) return;
    int rowBase = d_tileRowBase[rt];
    int nBase   = blockIdx.y * 128;

    const float* W = Wall + (size_t)e * K * N;

    __shared__ float As[8][128];
    __shared__ float Bs[8][128];

    int tid  = threadIdx.x;
    int aRow = tid >> 1;            // 0..127
    int aK   = (tid & 1) << 2;      // 0 or 4
    int bK   = tid >> 5;            // 0..7
    int bN   = (tid & 31) << 2;     // 0..124

    const float* arow;
    if (MODE == 0) {
        int tok = d_rowtok[rowBase + aRow];
        arow = (tok >= 0) ? (A + (size_t)tok * K) : 0;
    } else {
        arow = A + (size_t)(rowBase + aRow) * K;
    }
    const float* bptr = W + (size_t)bK * N + nBase + bN;

    float acc[8][8];
    #pragma unroll
    for (int i = 0; i < 8; i++)
        #pragma unroll
        for (int j = 0; j < 8; j++) acc[i][j] = 0.0f;

    int tx = tid & 15, ty = tid >> 4;
    int mSub = ty * 8, nSub = tx * 8;

    for (int k0 = 0; k0 < K; k0 += 8) {
        float4 av = arow ? *(const float4*)(arow + k0 + aK)
                         : make_float4(0.f, 0.f, 0.f, 0.f);
        float4 bv = *(const float4*)(bptr + (size_t)k0 * N);
        __syncthreads();
        As[aK + 0][aRow] = av.x;
        As[aK + 1][aRow] = av.y;
        As[aK + 2][aRow] = av.z;
        As[aK + 3][aRow] = av.w;
        *(float4*)&Bs[bK][bN] = bv;
        __syncthreads();
        #pragma unroll
        for (int k = 0; k < 8; k++) {
            float4 a0 = *(const float4*)&As[k][mSub];
            float4 a1 = *(const float4*)&As[k][mSub + 4];
            float4 b0 = *(const float4*)&Bs[k][nSub];
            float4 b1 = *(const float4*)&Bs[k][nSub + 4];
            float a[8] = {a0.x, a0.y, a0.z, a0.w, a1.x, a1.y, a1.z, a1.w};
            float bb[8] = {b0.x, b0.y, b0.z, b0.w, b1.x, b1.y, b1.z, b1.w};
            #pragma unroll
            for (int i = 0; i < 8; i++)
                #pragma unroll
                for (int j = 0; j < 8; j++)
                    acc[i][j] = fmaf(a[i], bb[j], acc[i][j]);
        }
    }

    if (MODE == 2) {
        #pragma unroll
        for (int i = 0; i < 8; i++) {
            int pr  = rowBase + mSub + i;
            int tok = d_rowtok[pr];
            if (tok < 0) continue;
            float g = d_rowgate[pr];
            float* orow = C + (size_t)tok * N + nBase + nSub;
            #pragma unroll
            for (int j = 0; j < 8; j++) {
                float v = acc[i][j] + Ball[e * N + nBase + nSub + j];
                atomicAdd(orow + j, g * v);
            }
        }
    } else {
        #pragma unroll
        for (int i = 0; i < 8; i++) {
            float* crow = C + (size_t)(rowBase + mSub + i) * N + nBase + nSub;
            #pragma unroll
            for (int j = 0; j < 8; j++) {
                float v = acc[i][j] + Ball[e * N + nBase + nSub + j];
                crow[j] = fmaxf(v, 0.0f);
            }
        }
    }
}

// ---------------- launch -----------------------------------------------------
extern "C" void kernel_launch(void* const* d_in, const int* in_sizes, int n_in,
                              void* d_out, int out_size) {
    const float* x  = (const float*)d_in[0];
    const float* Wr = (const float*)d_in[1];
    const float* br = (const float*)d_in[2];
    const float* W1 = (const float*)d_in[3];
    const float* b1 = (const float*)d_in[4];
    const float* W2 = (const float*)d_in[5];
    const float* b2 = (const float*)d_in[6];
    const float* W3 = (const float*)d_in[7];
    const float* b3 = (const float*)d_in[8];
    float* out = (float*)d_out;

    float *h1, *h2;
    cudaGetSymbolAddress((void**)&h1, d_h1);
    cudaGetSymbolAddress((void**)&h2, d_h2);

    init_kernel<<<12, 256>>>();
    router_kernel<<<B_TOK, 256>>>(x, Wr, br);
    scan_kernel<<<1, 32>>>();
    scatter_kernel<<<MAXPAIR / 256, 256>>>();
    zero_out_kernel<<<256, 256>>>(out);

    dim3 g1(MAXTILES, H_DIM / 128);
    moe_gemm_kernel<0><<<g1, 256>>>(x,  W1, b1, h1, D_DIM, H_DIM);
    dim3 g2(MAXTILES, H_DIM / 128);
    moe_gemm_kernel<1><<<g2, 256>>>(h1, W2, b2, h2, H_DIM, H_DIM);
    dim3 g3(MAXTILES, O_DIM / 128);
    moe_gemm_kernel<2><<<g3, 256>>>(h2, W3, b3, out, H_DIM, O_DIM);
}

// round 6
// speedup vs baseline: 3.6422x; 3.6422x over previous
#include <cuda_runtime.h>
#include <cuda_bf16.h>
#include <stdint.h>
#include <math.h>

typedef __nv_bfloat16 bf16;
typedef unsigned int u32;
typedef unsigned long long u64;

#define B_TOK   1024
#define D_DIM   1024
#define H_DIM   2048
#define O_DIM   1024
#define E_NUM   8
#define MAXPAIR 2048
#define TILE_M  128
#define MAXROWS 3072
#define MAXTILES 24

#define SW128(o) ((o) ^ (((o) >> 3) & 0x70))

// tcgen05 is arch-specific (sm_103a); plain sm_103 pass gets a scalar fallback.
#if defined(__CUDA_ARCH__) && (__CUDA_ARCH__ >= 1000) && \
    (defined(__CUDA_ARCH_FEAT_SM103_ALL) || defined(__CUDA_ARCH_FEAT_SM100_ALL) || \
     defined(__CUDA_ARCH_SPECIFIC__))
#define HAS_TCGEN05 1
#else
#define HAS_TCGEN05 0
#endif

// ---------------- device scratch (allocation-free) ---------------------------
__device__ bf16 g_xhi[B_TOK * D_DIM],  g_xlo[B_TOK * D_DIM];
__device__ bf16 g_w1hi[E_NUM * D_DIM * H_DIM], g_w1lo[E_NUM * D_DIM * H_DIM];
__device__ bf16 g_w2hi[E_NUM * H_DIM * H_DIM], g_w2lo[E_NUM * H_DIM * H_DIM];
__device__ bf16 g_w3hi[E_NUM * H_DIM * O_DIM], g_w3lo[E_NUM * H_DIM * O_DIM];
__device__ bf16 g_h1hi[MAXROWS * H_DIM], g_h1lo[MAXROWS * H_DIM];
__device__ bf16 g_h2hi[MAXROWS * H_DIM], g_h2lo[MAXROWS * H_DIM];
__device__ int   d_rowtok[MAXROWS];
__device__ float d_rowgate[MAXROWS];
__device__ int   d_counts[E_NUM];
__device__ int   d_fill[E_NUM];
__device__ int   d_tileExpert[MAXTILES];
__device__ int   d_tileRowBase[MAXTILES];
__device__ int   d_pairEid[MAXPAIR];
__device__ float d_pairGate[MAXPAIR];

// ---------------- PTX helpers ------------------------------------------------
__device__ __forceinline__ u32 smem_u32(const void* p) {
    u32 a;
    asm("{ .reg .u64 t; cvta.to.shared.u64 t, %1; cvt.u32.u64 %0, t; }"
        : "=r"(a) : "l"(p));
    return a;
}
__device__ __forceinline__ u32 elect_one() {
    u32 pred;
    asm volatile("{\n\t.reg .pred p;\n\telect.sync _|p, 0xFFFFFFFF;\n\t"
                 "selp.b32 %0, 1, 0, p;\n\t}" : "=r"(pred));
    return pred;
}
#define MBAR_INIT(a, c) \
    asm volatile("mbarrier.init.shared.b64 [%0], %1;" :: "r"(a), "r"(c) : "memory")
#define MBAR_INVAL(a) \
    asm volatile("mbarrier.inval.shared.b64 [%0];" :: "r"(a) : "memory")
__device__ __forceinline__ void mbar_wait(u32 mbar, u32 parity) {
    asm volatile(
        "{\n\t.reg .pred P;\n\t"
        "W_%=:\n\t"
        "mbarrier.try_wait.parity.acquire.cta.shared::cta.b64 P, [%0], %1, 0x989680;\n\t"
        "@P bra.uni D_%=;\n\t"
        "bra.uni W_%=;\n\t"
        "D_%=:\n\t}"
        :: "r"(mbar), "r"(parity) : "memory");
}

#if HAS_TCGEN05
#define TC_ALLOC(a, n) \
    asm volatile("tcgen05.alloc.cta_group::1.sync.aligned.shared::cta.b32 [%0], %1;" \
                 :: "r"(a), "r"(n) : "memory")
#define TC_DEALLOC(t, n) \
    asm volatile("tcgen05.dealloc.cta_group::1.sync.aligned.b32 %0, %1;" :: "r"(t), "r"(n))
#define TC_COMMIT(a) \
    asm volatile("tcgen05.commit.cta_group::1.mbarrier::arrive::one.shared::cluster.b64 [%0];" \
                 :: "r"(a) : "memory")
#define TC_FENCE_AFTER()  asm volatile("tcgen05.fence::after_thread_sync;" ::: "memory")
#define TC_FENCE_BEFORE() asm volatile("tcgen05.fence::before_thread_sync;" ::: "memory")
#define TC_WAIT_LD()      asm volatile("tcgen05.wait::ld.sync.aligned;" ::: "memory")
#define FENCE_ASYNC()     asm volatile("fence.proxy.async.shared::cta;" ::: "memory")

#define TC_LD_X32(r, addr) \
    asm volatile( \
        "tcgen05.ld.sync.aligned.32x32b.x32.b32 " \
        "{%0, %1, %2, %3, %4, %5, %6, %7, " \
        " %8, %9, %10, %11, %12, %13, %14, %15, " \
        " %16, %17, %18, %19, %20, %21, %22, %23, " \
        " %24, %25, %26, %27, %28, %29, %30, %31}, [%32];" \
        : "=r"((r)[0]),  "=r"((r)[1]),  "=r"((r)[2]),  "=r"((r)[3]), \
          "=r"((r)[4]),  "=r"((r)[5]),  "=r"((r)[6]),  "=r"((r)[7]), \
          "=r"((r)[8]),  "=r"((r)[9]),  "=r"((r)[10]), "=r"((r)[11]), \
          "=r"((r)[12]), "=r"((r)[13]), "=r"((r)[14]), "=r"((r)[15]), \
          "=r"((r)[16]), "=r"((r)[17]), "=r"((r)[18]), "=r"((r)[19]), \
          "=r"((r)[20]), "=r"((r)[21]), "=r"((r)[22]), "=r"((r)[23]), \
          "=r"((r)[24]), "=r"((r)[25]), "=r"((r)[26]), "=r"((r)[27]), \
          "=r"((r)[28]), "=r"((r)[29]), "=r"((r)[30]), "=r"((r)[31]) \
        : "r"(addr))

// SS-form cg1 f16 MMA
__device__ __forceinline__ void mma_f16_ss(u32 d, u64 a_desc, u64 b_desc,
                                           u32 idesc, u32 enable) {
    asm volatile(
        "{\n\t.reg .pred p;\n\tsetp.ne.u32 p, %4, 0;\n\t"
        "tcgen05.mma.cta_group::1.kind::f16 [%0], %1, %2, %3, {%5, %5, %5, %5}, p;\n\t}"
        :: "r"(d), "l"(a_desc), "l"(b_desc), "r"(idesc), "r"(enable), "r"(0u)
        : "memory");
}
#endif // HAS_TCGEN05

// SW128 K-major SMEM descriptor (Blackwell)
#define SMEM_DESC_BASE \
    ((2ULL << 61) | (1ULL << 46) | (64ULL << 32) | (1ULL << 16))
#define MKDESC(addr) (SMEM_DESC_BASE | ((u64)((addr) >> 4) & 0x3FFF))

// idesc: F32 accum, BF16 x BF16, M=128, N=128
#define IDESC_128x128 0x8200490u

// ---------------- routing kernels --------------------------------------------
__global__ void init_kernel() {
    int t = blockIdx.x * blockDim.x + threadIdx.x;
    if (t < E_NUM) d_counts[t] = 0;
    for (int i = t; i < MAXROWS; i += gridDim.x * blockDim.x) {
        d_rowtok[i]  = -1;
        d_rowgate[i] = 0.0f;
    }
}

__global__ void router_kernel(const float* __restrict__ x,
                              const float* __restrict__ Wr,
                              const float* __restrict__ br) {
    __shared__ float xs[D_DIM];
    __shared__ float lg[E_NUM];
    int b = blockIdx.x;
    const float* xr = x + (size_t)b * D_DIM;
    for (int i = threadIdx.x; i < D_DIM; i += 256) xs[i] = xr[i];
    __syncthreads();

    int warp = threadIdx.x >> 5, lane = threadIdx.x & 31;
    float s = 0.0f;
    for (int d = lane; d < D_DIM; d += 32) s += xs[d] * Wr[d * E_NUM + warp];
    #pragma unroll
    for (int o = 16; o > 0; o >>= 1) s += __shfl_down_sync(0xffffffffu, s, o);
    if (lane == 0) lg[warp] = s + br[warp];
    __syncthreads();

    if (threadIdx.x == 0) {
        float m = lg[0];
        #pragma unroll
        for (int e = 1; e < E_NUM; e++) m = fmaxf(m, lg[e]);
        float p[E_NUM]; float sum = 0.0f;
        #pragma unroll
        for (int e = 0; e < E_NUM; e++) { p[e] = expf(lg[e] - m); sum += p[e]; }
        int i0 = 0;
        #pragma unroll
        for (int e = 1; e < E_NUM; e++) if (p[e] > p[i0]) i0 = e;
        int i1 = (i0 == 0) ? 1 : 0;
        #pragma unroll
        for (int e = 0; e < E_NUM; e++) if (e != i0 && p[e] > p[i1]) i1 = e;
        float w0 = p[i0] / sum, w1 = p[i1] / sum;
        float den = w0 + w1 + 1e-6f;
        d_pairEid[b * 2 + 0] = i0;  d_pairGate[b * 2 + 0] = w0 / den;
        d_pairEid[b * 2 + 1] = i1;  d_pairGate[b * 2 + 1] = w1 / den;
        atomicAdd(&d_counts[i0], 1);
        atomicAdd(&d_counts[i1], 1);
    }
}

__global__ void scan_kernel() {
    if (threadIdx.x != 0 || blockIdx.x != 0) return;
    int off = 0, rt = 0;
    for (int e = 0; e < E_NUM; e++) {
        int c  = d_counts[e];
        int pc = (c + TILE_M - 1) / TILE_M * TILE_M;
        d_fill[e] = off;
        for (int t = 0; t < pc / TILE_M; t++) {
            d_tileExpert[rt]  = e;
            d_tileRowBase[rt] = off + t * TILE_M;
            rt++;
        }
        off += pc;
    }
    for (; rt < MAXTILES; rt++) d_tileExpert[rt] = -1;
}

__global__ void scatter_kernel() {
    int p = blockIdx.x * blockDim.x + threadIdx.x;
    if (p >= MAXPAIR) return;
    int e   = d_pairEid[p];
    int pos = atomicAdd(&d_fill[e], 1);
    d_rowtok[pos]  = p >> 1;
    d_rowgate[pos] = d_pairGate[p];
}

__global__ void zero_out_kernel(float* __restrict__ out) {
    int n = B_TOK * O_DIM;
    for (int i = blockIdx.x * blockDim.x + threadIdx.x; i < n;
         i += gridDim.x * blockDim.x)
        out[i] = 0.0f;
}

// ---------------- pre-pass: x -> split bf16 ----------------------------------
__global__ void convert_x_kernel(const float* __restrict__ x,
                                 bf16* __restrict__ xhi, bf16* __restrict__ xlo) {
    int idx = blockIdx.x * 256 + threadIdx.x;
    float4 v = ((const float4*)x)[idx];
    float vv[4] = {v.x, v.y, v.z, v.w};
    u32 hp[2], lp[2];
    #pragma unroll
    for (int j = 0; j < 2; j++) {
        bf16 h0 = __float2bfloat16(vv[2 * j]);
        bf16 h1 = __float2bfloat16(vv[2 * j + 1]);
        bf16 l0 = __float2bfloat16(vv[2 * j]     - __bfloat162float(h0));
        bf16 l1 = __float2bfloat16(vv[2 * j + 1] - __bfloat162float(h1));
        hp[j] = ((u32)__bfloat16_as_ushort(h1) << 16) | __bfloat16_as_ushort(h0);
        lp[j] = ((u32)__bfloat16_as_ushort(l1) << 16) | __bfloat16_as_ushort(l0);
    }
    ((uint2*)xhi)[idx] = make_uint2(hp[0], hp[1]);
    ((uint2*)xlo)[idx] = make_uint2(lp[0], lp[1]);
}

// ---------------- pre-pass: W[e][k][n] -> transposed swizzled split tiles ----
__global__ void convert_w_kernel(const float* __restrict__ W,
                                 bf16* __restrict__ outHi, bf16* __restrict__ outLo,
                                 int K, int N) {
    __shared__ float s[64][129];
    int tid = threadIdx.x;
    int kc = blockIdx.x, nt = blockIdx.y, e = blockIdx.z;
    const float* Wexp = W + (size_t)e * K * N;

    #pragma unroll
    for (int i = 0; i < 8; i++) {
        int u  = tid + 256 * i;
        int k  = u >> 5;
        int n4 = u & 31;
        float4 v = *(const float4*)(Wexp + (size_t)(kc * 64 + k) * N + nt * 128 + n4 * 4);
        s[k][n4 * 4 + 0] = v.x;
        s[k][n4 * 4 + 1] = v.y;
        s[k][n4 * 4 + 2] = v.z;
        s[k][n4 * 4 + 3] = v.w;
    }
    __syncthreads();

    size_t tileByte = ((size_t)(e * gridDim.y + nt) * gridDim.x + kc) * 16384;
    #pragma unroll
    for (int i = 0; i < 4; i++) {
        int u = tid + 256 * i;
        int r = u >> 3;
        int c = u & 7;
        u32 hp[4], lp[4];
        #pragma unroll
        for (int j = 0; j < 4; j++) {
            float v0 = s[c * 8 + 2 * j][r];
            float v1 = s[c * 8 + 2 * j + 1][r];
            bf16 h0 = __float2bfloat16(v0);
            bf16 h1 = __float2bfloat16(v1);
            bf16 l0 = __float2bfloat16(v0 - __bfloat162float(h0));
            bf16 l1 = __float2bfloat16(v1 - __bfloat162float(h1));
            hp[j] = ((u32)__bfloat16_as_ushort(h1) << 16) | __bfloat16_as_ushort(h0);
            lp[j] = ((u32)__bfloat16_as_ushort(l1) << 16) | __bfloat16_as_ushort(l0);
        }
        u32 off = SW128((u32)(r * 128 + c * 16));
        *(uint4*)((char*)outHi + tileByte + off) = make_uint4(hp[0], hp[1], hp[2], hp[3]);
        *(uint4*)((char*)outLo + tileByte + off) = make_uint4(lp[0], lp[1], lp[2], lp[3]);
    }
}

// ---------------- grouped GEMM (tensor path on sm_103a, scalar otherwise) ----
#define SM_TMEMPTR 0
#define SM_MBAR    16
#define SM_AHI     1024
#define SM_ALO     (SM_AHI + 16384)
#define SM_BHI     (SM_ALO + 16384)
#define SM_BLO     (SM_BHI + 16384)
#define SMEM_BYTES (SM_BLO + 16384)

template <int MODE>
__global__ __launch_bounds__(256, 1) __cluster_dims__(1, 1, 1)
void tc_gemm(const bf16* __restrict__ Ahi, const bf16* __restrict__ Alo,
             const bf16* __restrict__ Whi, const bf16* __restrict__ Wlo,
             const float* __restrict__ Ball,
             bf16* __restrict__ Chi, bf16* __restrict__ Clo,
             float* __restrict__ Out,
             int K, int N) {
    int rt = blockIdx.x;
    int e  = d_tileExpert[rt];
    if (e < 0) return;
    int rowBase = d_tileRowBase[rt];
    int NT      = gridDim.y;
    int nBase   = blockIdx.y * 128;
    int KC      = K >> 6;
    int tid     = threadIdx.x;
    size_t wTile = ((size_t)(e * NT + blockIdx.y) * KC) * 16384;  // bytes

#if HAS_TCGEN05
    extern __shared__ char smem[];
    u32 sb  = smem_u32(smem);
    int wid = tid >> 5, lane = tid & 31;

    if (wid == 0) TC_ALLOC(sb + SM_TMEMPTR, 128);
    if (tid == 0) MBAR_INIT(sb + SM_MBAR, 1);
    __syncthreads();
    u32 tmem;
    asm volatile("ld.shared.b32 %0, [%1];" : "=r"(tmem) : "r"(sb + SM_TMEMPTR));

    const bf16* aH[4];
    const bf16* aL[4];
    u32 aSts[4];
    #pragma unroll
    for (int i = 0; i < 4; i++) {
        int u = tid + 256 * i;
        int r = u >> 3, c = u & 7;
        int grow;
        if (MODE == 0) grow = d_rowtok[rowBase + r];
        else           grow = rowBase + r;
        if (grow >= 0) {
            aH[i] = Ahi + (size_t)grow * K + c * 8;
            aL[i] = Alo + (size_t)grow * K + c * 8;
        } else { aH[i] = 0; aL[i] = 0; }
        aSts[i] = SW128((u32)(r * 128 + c * 16));
    }

    u64 dAh = MKDESC(sb + SM_AHI);
    u64 dAl = MKDESC(sb + SM_ALO);
    u64 dBh = MKDESC(sb + SM_BHI);
    u64 dBl = MKDESC(sb + SM_BLO);

    for (int kc = 0; kc < KC; kc++) {
        if (kc > 0) mbar_wait(sb + SM_MBAR, (kc - 1) & 1);

        #pragma unroll
        for (int i = 0; i < 4; i++) {
            uint4 vh = aH[i] ? *(const uint4*)(aH[i] + kc * 64)
                             : make_uint4(0, 0, 0, 0);
            uint4 vl = aL[i] ? *(const uint4*)(aL[i] + kc * 64)
                             : make_uint4(0, 0, 0, 0);
            *(uint4*)(smem + SM_AHI + aSts[i]) = vh;
            *(uint4*)(smem + SM_ALO + aSts[i]) = vl;
        }
        {
            const char* srcH = (const char*)Whi + wTile + (size_t)kc * 16384;
            const char* srcL = (const char*)Wlo + wTile + (size_t)kc * 16384;
            #pragma unroll
            for (int i = 0; i < 4; i++) {
                int u = tid + 256 * i;
                *(uint4*)(smem + SM_BHI + u * 16) = *(const uint4*)(srcH + u * 16);
                *(uint4*)(smem + SM_BLO + u * 16) = *(const uint4*)(srcL + u * 16);
            }
        }
        FENCE_ASYNC();
        __syncthreads();

        if (wid == 0 && elect_one()) {
            #pragma unroll
            for (int s = 0; s < 4; s++) {
                u32 en0 = (kc == 0 && s == 0) ? 0u : 1u;
                mma_f16_ss(tmem, dAh + 2 * s, dBh + 2 * s, IDESC_128x128, en0);
                mma_f16_ss(tmem, dAl + 2 * s, dBh + 2 * s, IDESC_128x128, 1u);
                mma_f16_ss(tmem, dAh + 2 * s, dBl + 2 * s, IDESC_128x128, 1u);
            }
            TC_COMMIT(sb + SM_MBAR);
        }
    }

    mbar_wait(sb + SM_MBAR, (KC - 1) & 1);
    TC_FENCE_AFTER();

    // ---- epilogue: ONLY warps 0-3 (TMEM D has 128 lanes = 4 subpartitions;
    // warp w reads lanes w*32..w*32+31 = tile rows w*32..w*32+31). Warps 4-7
    // reading TMEM would see duplicated subpartitions and write rows past the
    // 128-row tile — that was the round-5 corruption. ----
    if (wid < 4) {
        const float* bias = Ball + (size_t)e * N + nBase;
        int pr = rowBase + wid * 32 + lane;

        if (MODE == 2) {
            int tok  = d_rowtok[pr];
            float gt = d_rowgate[pr];
            float* orow = (tok >= 0) ? (Out + (size_t)tok * N + nBase) : 0;
            #pragma unroll
            for (int cb = 0; cb < 128; cb += 32) {
                u32 dreg[32];
                TC_LD_X32(dreg, tmem + cb);
                TC_WAIT_LD();
                if (orow) {
                    #pragma unroll
                    for (int c = 0; c < 32; c++) {
                        float v = __uint_as_float(dreg[c]) + __ldg(bias + cb + c);
                        atomicAdd(orow + cb + c, gt * v);
                    }
                }
            }
        } else {
            size_t rowoff = (size_t)pr * N + nBase;
            #pragma unroll
            for (int cb = 0; cb < 128; cb += 32) {
                u32 dreg[32];
                TC_LD_X32(dreg, tmem + cb);
                TC_WAIT_LD();
                #pragma unroll
                for (int g = 0; g < 4; g++) {
                    u32 hp[4], lp[4];
                    #pragma unroll
                    for (int j = 0; j < 4; j++) {
                        int c0 = g * 8 + 2 * j;
                        float v0 = __uint_as_float(dreg[c0])     + __ldg(bias + cb + c0);
                        float v1 = __uint_as_float(dreg[c0 + 1]) + __ldg(bias + cb + c0 + 1);
                        v0 = fmaxf(v0, 0.0f);
                        v1 = fmaxf(v1, 0.0f);
                        bf16 h0 = __float2bfloat16(v0);
                        bf16 h1 = __float2bfloat16(v1);
                        bf16 l0 = __float2bfloat16(v0 - __bfloat162float(h0));
                        bf16 l1 = __float2bfloat16(v1 - __bfloat162float(h1));
                        hp[j] = ((u32)__bfloat16_as_ushort(h1) << 16) | __bfloat16_as_ushort(h0);
                        lp[j] = ((u32)__bfloat16_as_ushort(l1) << 16) | __bfloat16_as_ushort(l0);
                    }
                    *(uint4*)(Chi + rowoff + cb + g * 8) = make_uint4(hp[0], hp[1], hp[2], hp[3]);
                    *(uint4*)(Clo + rowoff + cb + g * 8) = make_uint4(lp[0], lp[1], lp[2], lp[3]);
                }
            }
        }
        TC_FENCE_BEFORE();
    }

    __syncthreads();
    if (tid == 0) MBAR_INVAL(sb + SM_MBAR);
    __syncthreads();
    if (wid == 0) TC_DEALLOC(tmem, 128);

#else
    // -------- scalar fallback (plain sm_103 pass; correct, not fast) --------
    int tx = tid & 15, ty = tid >> 4;
    int mSub = ty * 8, nSub = tx * 8;

    const bf16 *ah[8], *al[8];
    #pragma unroll
    for (int i = 0; i < 8; i++) {
        int r = mSub + i;
        int grow;
        if (MODE == 0) grow = d_rowtok[rowBase + r];
        else           grow = rowBase + r;
        if (grow >= 0) {
            ah[i] = Ahi + (size_t)grow * K;
            al[i] = Alo + (size_t)grow * K;
        } else { ah[i] = 0; al[i] = 0; }
    }

    float acc[8][8];
    #pragma unroll
    for (int i = 0; i < 8; i++)
        #pragma unroll
        for (int j = 0; j < 8; j++) acc[i][j] = 0.0f;

    for (int k = 0; k < K; k++) {
        int kc = k >> 6, kk = k & 63;
        const char* bH = (const char*)Whi + wTile + (size_t)kc * 16384;
        const char* bL = (const char*)Wlo + wTile + (size_t)kc * 16384;
        float bv[8];
        #pragma unroll
        for (int j = 0; j < 8; j++) {
            int n = nSub + j;
            u32 off = SW128((u32)(n * 128 + (kk >> 3) * 16)) + (kk & 7) * 2;
            bv[j] = __bfloat162float(*(const bf16*)(bH + off)) +
                    __bfloat162float(*(const bf16*)(bL + off));
        }
        #pragma unroll
        for (int i = 0; i < 8; i++) {
            float a = ah[i] ? (__bfloat162float(__ldg(ah[i] + k)) +
                               __bfloat162float(__ldg(al[i] + k))) : 0.0f;
            #pragma unroll
            for (int j = 0; j < 8; j++) acc[i][j] = fmaf(a, bv[j], acc[i][j]);
        }
    }

    const float* bias = Ball + (size_t)e * N + nBase;
    if (MODE == 2) {
        #pragma unroll
        for (int i = 0; i < 8; i++) {
            int pr  = rowBase + mSub + i;
            int tok = d_rowtok[pr];
            if (tok < 0) continue;
            float g = d_rowgate[pr];
            float* orow = Out + (size_t)tok * N + nBase;
            #pragma unroll
            for (int j = 0; j < 8; j++) {
                float v = acc[i][j] + bias[nSub + j];
                atomicAdd(orow + nSub + j, g * v);
            }
        }
    } else {
        #pragma unroll
        for (int i = 0; i < 8; i++) {
            int pr = rowBase + mSub + i;
            size_t rowoff = (size_t)pr * N + nBase;
            #pragma unroll
            for (int j = 0; j < 8; j++) {
                float v = fmaxf(acc[i][j] + bias[nSub + j], 0.0f);
                bf16 h = __float2bfloat16(v);
                bf16 l = __float2bfloat16(v - __bfloat162float(h));
                Chi[rowoff + nSub + j] = h;
                Clo[rowoff + nSub + j] = l;
            }
        }
    }
#endif
}

// ---------------- launch -----------------------------------------------------
extern "C" void kernel_launch(void* const* d_in, const int* in_sizes, int n_in,
                              void* d_out, int out_size) {
    const float* x  = (const float*)d_in[0];
    const float* Wr = (const float*)d_in[1];
    const float* br = (const float*)d_in[2];
    const float* W1 = (const float*)d_in[3];
    const float* b1 = (const float*)d_in[4];
    const float* W2 = (const float*)d_in[5];
    const float* b2 = (const float*)d_in[6];
    const float* W3 = (const float*)d_in[7];
    const float* b3 = (const float*)d_in[8];
    float* out = (float*)d_out;

    bf16 *xhi, *xlo, *w1h, *w1l, *w2h, *w2l, *w3h, *w3l, *h1h, *h1l, *h2h, *h2l;
    cudaGetSymbolAddress((void**)&xhi, g_xhi);
    cudaGetSymbolAddress((void**)&xlo, g_xlo);
    cudaGetSymbolAddress((void**)&w1h, g_w1hi);
    cudaGetSymbolAddress((void**)&w1l, g_w1lo);
    cudaGetSymbolAddress((void**)&w2h, g_w2hi);
    cudaGetSymbolAddress((void**)&w2l, g_w2lo);
    cudaGetSymbolAddress((void**)&w3h, g_w3hi);
    cudaGetSymbolAddress((void**)&w3l, g_w3lo);
    cudaGetSymbolAddress((void**)&h1h, g_h1hi);
    cudaGetSymbolAddress((void**)&h1l, g_h1lo);
    cudaGetSymbolAddress((void**)&h2h, g_h2hi);
    cudaGetSymbolAddress((void**)&h2l, g_h2lo);

    cudaFuncSetAttribute(tc_gemm<0>, cudaFuncAttributeMaxDynamicSharedMemorySize, SMEM_BYTES);
    cudaFuncSetAttribute(tc_gemm<1>, cudaFuncAttributeMaxDynamicSharedMemorySize, SMEM_BYTES);
    cudaFuncSetAttribute(tc_gemm<2>, cudaFuncAttributeMaxDynamicSharedMemorySize, SMEM_BYTES);

    init_kernel<<<12, 256>>>();
    router_kernel<<<B_TOK, 256>>>(x, Wr, br);
    scan_kernel<<<1, 32>>>();
    scatter_kernel<<<MAXPAIR / 256, 256>>>();
    zero_out_kernel<<<256, 256>>>(out);

    convert_x_kernel<<<B_TOK * D_DIM / 1024, 256>>>(x, xhi, xlo);
    convert_w_kernel<<<dim3(D_DIM / 64, H_DIM / 128, E_NUM), 256>>>(W1, w1h, w1l, D_DIM, H_DIM);
    convert_w_kernel<<<dim3(H_DIM / 64, H_DIM / 128, E_NUM), 256>>>(W2, w2h, w2l, H_DIM, H_DIM);
    convert_w_kernel<<<dim3(H_DIM / 64, O_DIM / 128, E_NUM), 256>>>(W3, w3h, w3l, H_DIM, O_DIM);

    tc_gemm<0><<<dim3(MAXTILES, H_DIM / 128), 256, SMEM_BYTES>>>(
        xhi, xlo, w1h, w1l, b1, h1h, h1l, 0, D_DIM, H_DIM);
    tc_gemm<1><<<dim3(MAXTILES, H_DIM / 128), 256, SMEM_BYTES>>>(
        h1h, h1l, w2h, w2l, b2, h2h, h2l, 0, H_DIM, H_DIM);
    tc_gemm<2><<<dim3(MAXTILES, O_DIM / 128), 256, SMEM_BYTES>>>(
        h2h, h2l, w3h, w3l, b3, 0, 0, out, H_DIM, O_DIM);
}

// round 8
// speedup vs baseline: 3.9953x; 1.0969x over previous
#include <cuda_runtime.h>
#include <cuda_bf16.h>
#include <stdint.h>
#include <math.h>

typedef __nv_bfloat16 bf16;
typedef unsigned int u32;
typedef unsigned long long u64;

#define B_TOK   1024
#define D_DIM   1024
#define H_DIM   2048
#define O_DIM   1024
#define E_NUM   8
#define MAXPAIR 2048
#define TILE_M  128
#define MAXROWS 3072
#define MAXTILES 24

#define SW128(o) ((o) ^ (((o) >> 3) & 0x70))

// tcgen05 is arch-specific (sm_103a); plain sm_103 pass gets a scalar fallback.
#if defined(__CUDA_ARCH__) && (__CUDA_ARCH__ >= 1000) && \
    (defined(__CUDA_ARCH_FEAT_SM103_ALL) || defined(__CUDA_ARCH_FEAT_SM100_ALL) || \
     defined(__CUDA_ARCH_SPECIFIC__))
#define HAS_TCGEN05 1
#else
#define HAS_TCGEN05 0
#endif

// ---------------- device scratch (allocation-free) ---------------------------
__device__ bf16 g_xhi[B_TOK * D_DIM],  g_xlo[B_TOK * D_DIM];
__device__ bf16 g_w1hi[E_NUM * D_DIM * H_DIM], g_w1lo[E_NUM * D_DIM * H_DIM];
__device__ bf16 g_w2hi[E_NUM * H_DIM * H_DIM], g_w2lo[E_NUM * H_DIM * H_DIM];
__device__ bf16 g_w3hi[E_NUM * H_DIM * O_DIM], g_w3lo[E_NUM * H_DIM * O_DIM];
__device__ bf16 g_h1hi[MAXROWS * H_DIM], g_h1lo[MAXROWS * H_DIM];
__device__ bf16 g_h2hi[MAXROWS * H_DIM], g_h2lo[MAXROWS * H_DIM];
__device__ int   d_rowtok[MAXROWS];
__device__ float d_rowgate[MAXROWS];
__device__ int   d_counts[E_NUM];
__device__ int   d_fill[E_NUM];
__device__ int   d_tileExpert[MAXTILES];
__device__ int   d_tileRowBase[MAXTILES];
__device__ int   d_pairEid[MAXPAIR];
__device__ float d_pairGate[MAXPAIR];

// ---------------- PTX helpers ------------------------------------------------
__device__ __forceinline__ u32 smem_u32(const void* p) {
    u32 a;
    asm("{ .reg .u64 t; cvta.to.shared.u64 t, %1; cvt.u32.u64 %0, t; }"
        : "=r"(a) : "l"(p));
    return a;
}
__device__ __forceinline__ u32 elect_one() {
    u32 pred;
    asm volatile("{\n\t.reg .pred p;\n\telect.sync _|p, 0xFFFFFFFF;\n\t"
                 "selp.b32 %0, 1, 0, p;\n\t}" : "=r"(pred));
    return pred;
}
#define MBAR_INIT(a, c) \
    asm volatile("mbarrier.init.shared.b64 [%0], %1;" :: "r"(a), "r"(c) : "memory")
#define MBAR_INVAL(a) \
    asm volatile("mbarrier.inval.shared.b64 [%0];" :: "r"(a) : "memory")
__device__ __forceinline__ void mbar_wait(u32 mbar, u32 parity) {
    asm volatile(
        "{\n\t.reg .pred P;\n\t"
        "W_%=:\n\t"
        "mbarrier.try_wait.parity.acquire.cta.shared::cta.b64 P, [%0], %1, 0x989680;\n\t"
        "@P bra.uni D_%=;\n\t"
        "bra.uni W_%=;\n\t"
        "D_%=:\n\t}"
        :: "r"(mbar), "r"(parity) : "memory");
}

#if HAS_TCGEN05
#define TC_ALLOC(a, n) \
    asm volatile("tcgen05.alloc.cta_group::1.sync.aligned.shared::cta.b32 [%0], %1;" \
                 :: "r"(a), "r"(n) : "memory")
#define TC_DEALLOC(t, n) \
    asm volatile("tcgen05.dealloc.cta_group::1.sync.aligned.b32 %0, %1;" :: "r"(t), "r"(n))
#define TC_COMMIT(a) \
    asm volatile("tcgen05.commit.cta_group::1.mbarrier::arrive::one.shared::cluster.b64 [%0];" \
                 :: "r"(a) : "memory")
#define TC_FENCE_AFTER()  asm volatile("tcgen05.fence::after_thread_sync;" ::: "memory")
#define TC_FENCE_BEFORE() asm volatile("tcgen05.fence::before_thread_sync;" ::: "memory")
#define TC_WAIT_LD()      asm volatile("tcgen05.wait::ld.sync.aligned;" ::: "memory")
#define FENCE_ASYNC()     asm volatile("fence.proxy.async.shared::cta;" ::: "memory")

#define TC_LD_X32(r, addr) \
    asm volatile( \
        "tcgen05.ld.sync.aligned.32x32b.x32.b32 " \
        "{%0, %1, %2, %3, %4, %5, %6, %7, " \
        " %8, %9, %10, %11, %12, %13, %14, %15, " \
        " %16, %17, %18, %19, %20, %21, %22, %23, " \
        " %24, %25, %26, %27, %28, %29, %30, %31}, [%32];" \
        : "=r"((r)[0]),  "=r"((r)[1]),  "=r"((r)[2]),  "=r"((r)[3]), \
          "=r"((r)[4]),  "=r"((r)[5]),  "=r"((r)[6]),  "=r"((r)[7]), \
          "=r"((r)[8]),  "=r"((r)[9]),  "=r"((r)[10]), "=r"((r)[11]), \
          "=r"((r)[12]), "=r"((r)[13]), "=r"((r)[14]), "=r"((r)[15]), \
          "=r"((r)[16]), "=r"((r)[17]), "=r"((r)[18]), "=r"((r)[19]), \
          "=r"((r)[20]), "=r"((r)[21]), "=r"((r)[22]), "=r"((r)[23]), \
          "=r"((r)[24]), "=r"((r)[25]), "=r"((r)[26]), "=r"((r)[27]), \
          "=r"((r)[28]), "=r"((r)[29]), "=r"((r)[30]), "=r"((r)[31]) \
        : "r"(addr))

// SS-form cg1 f16 MMA
__device__ __forceinline__ void mma_f16_ss(u32 d, u64 a_desc, u64 b_desc,
                                           u32 idesc, u32 enable) {
    asm volatile(
        "{\n\t.reg .pred p;\n\tsetp.ne.u32 p, %4, 0;\n\t"
        "tcgen05.mma.cta_group::1.kind::f16 [%0], %1, %2, %3, {%5, %5, %5, %5}, p;\n\t}"
        :: "r"(d), "l"(a_desc), "l"(b_desc), "r"(idesc), "r"(enable), "r"(0u)
        : "memory");
}
#endif // HAS_TCGEN05

// SW128 K-major SMEM descriptor (Blackwell)
#define SMEM_DESC_BASE \
    ((2ULL << 61) | (1ULL << 46) | (64ULL << 32) | (1ULL << 16))
#define MKDESC(addr) (SMEM_DESC_BASE | ((u64)((addr) >> 4) & 0x3FFF))

// idesc: F32 accum, BF16 x BF16, M=128, N=128
#define IDESC_128x128 0x8200490u

// ---------------- routing kernels --------------------------------------------
__global__ void init_kernel() {
    int t = blockIdx.x * blockDim.x + threadIdx.x;
    if (t < E_NUM) d_counts[t] = 0;
    for (int i = t; i < MAXROWS; i += gridDim.x * blockDim.x) {
        d_rowtok[i]  = -1;
        d_rowgate[i] = 0.0f;
    }
}

__global__ void router_kernel(const float* __restrict__ x,
                              const float* __restrict__ Wr,
                              const float* __restrict__ br) {
    __shared__ float xs[D_DIM];
    __shared__ float lg[E_NUM];
    int b = blockIdx.x;
    const float* xr = x + (size_t)b * D_DIM;
    for (int i = threadIdx.x; i < D_DIM; i += 256) xs[i] = xr[i];
    __syncthreads();

    int warp = threadIdx.x >> 5, lane = threadIdx.x & 31;
    float s = 0.0f;
    for (int d = lane; d < D_DIM; d += 32) s += xs[d] * Wr[d * E_NUM + warp];
    #pragma unroll
    for (int o = 16; o > 0; o >>= 1) s += __shfl_down_sync(0xffffffffu, s, o);
    if (lane == 0) lg[warp] = s + br[warp];
    __syncthreads();

    if (threadIdx.x == 0) {
        float m = lg[0];
        #pragma unroll
        for (int e = 1; e < E_NUM; e++) m = fmaxf(m, lg[e]);
        float p[E_NUM]; float sum = 0.0f;
        #pragma unroll
        for (int e = 0; e < E_NUM; e++) { p[e] = expf(lg[e] - m); sum += p[e]; }
        int i0 = 0;
        #pragma unroll
        for (int e = 1; e < E_NUM; e++) if (p[e] > p[i0]) i0 = e;
        int i1 = (i0 == 0) ? 1 : 0;
        #pragma unroll
        for (int e = 0; e < E_NUM; e++) if (e != i0 && p[e] > p[i1]) i1 = e;
        float w0 = p[i0] / sum, w1 = p[i1] / sum;
        float den = w0 + w1 + 1e-6f;
        d_pairEid[b * 2 + 0] = i0;  d_pairGate[b * 2 + 0] = w0 / den;
        d_pairEid[b * 2 + 1] = i1;  d_pairGate[b * 2 + 1] = w1 / den;
        atomicAdd(&d_counts[i0], 1);
        atomicAdd(&d_counts[i1], 1);
    }
}

__global__ void scan_kernel() {
    if (threadIdx.x != 0 || blockIdx.x != 0) return;
    int off = 0, rt = 0;
    for (int e = 0; e < E_NUM; e++) {
        int c  = d_counts[e];
        int pc = (c + TILE_M - 1) / TILE_M * TILE_M;
        d_fill[e] = off;
        for (int t = 0; t < pc / TILE_M; t++) {
            d_tileExpert[rt]  = e;
            d_tileRowBase[rt] = off + t * TILE_M;
            rt++;
        }
        off += pc;
    }
    for (; rt < MAXTILES; rt++) d_tileExpert[rt] = -1;
}

__global__ void scatter_kernel() {
    int p = blockIdx.x * blockDim.x + threadIdx.x;
    if (p >= MAXPAIR) return;
    int e   = d_pairEid[p];
    int pos = atomicAdd(&d_fill[e], 1);
    d_rowtok[pos]  = p >> 1;
    d_rowgate[pos] = d_pairGate[p];
}

// ---------------- pre-pass: x -> split bf16 ----------------------------------
__global__ void convert_x_kernel(const float* __restrict__ x,
                                 bf16* __restrict__ xhi, bf16* __restrict__ xlo) {
    int idx = blockIdx.x * 256 + threadIdx.x;
    float4 v = ((const float4*)x)[idx];
    float vv[4] = {v.x, v.y, v.z, v.w};
    u32 hp[2], lp[2];
    #pragma unroll
    for (int j = 0; j < 2; j++) {
        bf16 h0 = __float2bfloat16(vv[2 * j]);
        bf16 h1 = __float2bfloat16(vv[2 * j + 1]);
        bf16 l0 = __float2bfloat16(vv[2 * j]     - __bfloat162float(h0));
        bf16 l1 = __float2bfloat16(vv[2 * j + 1] - __bfloat162float(h1));
        hp[j] = ((u32)__bfloat16_as_ushort(h1) << 16) | __bfloat16_as_ushort(h0);
        lp[j] = ((u32)__bfloat16_as_ushort(l1) << 16) | __bfloat16_as_ushort(l0);
    }
    ((uint2*)xhi)[idx] = make_uint2(hp[0], hp[1]);
    ((uint2*)xlo)[idx] = make_uint2(lp[0], lp[1]);
}

// ---------------- pre-pass: W[e][k][n] -> transposed swizzled split tiles ----
// Tile t = ((e*NT + nt)*KC + kc): byte image of a 128n x 64k bf16 SW128 tile.
__global__ void convert_w_kernel(const float* __restrict__ W,
                                 bf16* __restrict__ outHi, bf16* __restrict__ outLo,
                                 int K, int N) {
    __shared__ float s[64][129];
    int tid = threadIdx.x;
    int kc = blockIdx.x, nt = blockIdx.y, e = blockIdx.z;
    const float* Wexp = W + (size_t)e * K * N;

    #pragma unroll
    for (int i = 0; i < 8; i++) {
        int u  = tid + 256 * i;
        int k  = u >> 5;
        int n4 = u & 31;
        float4 v = *(const float4*)(Wexp + (size_t)(kc * 64 + k) * N + nt * 128 + n4 * 4);
        s[k][n4 * 4 + 0] = v.x;
        s[k][n4 * 4 + 1] = v.y;
        s[k][n4 * 4 + 2] = v.z;
        s[k][n4 * 4 + 3] = v.w;
    }
    __syncthreads();

    size_t tileByte = ((size_t)(e * gridDim.y + nt) * gridDim.x + kc) * 16384;
    #pragma unroll
    for (int i = 0; i < 4; i++) {
        int u = tid + 256 * i;
        int r = u >> 3;
        int c = u & 7;
        u32 hp[4], lp[4];
        #pragma unroll
        for (int j = 0; j < 4; j++) {
            float v0 = s[c * 8 + 2 * j][r];
            float v1 = s[c * 8 + 2 * j + 1][r];
            bf16 h0 = __float2bfloat16(v0);
            bf16 h1 = __float2bfloat16(v1);
            bf16 l0 = __float2bfloat16(v0 - __bfloat162float(h0));
            bf16 l1 = __float2bfloat16(v1 - __bfloat162float(h1));
            hp[j] = ((u32)__bfloat16_as_ushort(h1) << 16) | __bfloat16_as_ushort(h0);
            lp[j] = ((u32)__bfloat16_as_ushort(l1) << 16) | __bfloat16_as_ushort(l0);
        }
        u32 off = SW128((u32)(r * 128 + c * 16));
        *(uint4*)((char*)outHi + tileByte + off) = make_uint4(hp[0], hp[1], hp[2], hp[3]);
        *(uint4*)((char*)outLo + tileByte + off) = make_uint4(lp[0], lp[1], lp[2], lp[3]);
    }
}

// ---------------- grouped GEMM: M128 x N256 per CTA, K-chunk 64 --------------
// Two 128-col D tiles in TMEM (cols 0-127, 128-255) share the A SMEM tile.
#define SM_TMEMPTR 0
#define SM_MBAR    16
#define SM_AHI     1024
#define SM_ALO     (SM_AHI  + 16384)
#define SM_B0HI    (SM_ALO  + 16384)
#define SM_B0LO    (SM_B0HI + 16384)
#define SM_B1HI    (SM_B0LO + 16384)
#define SM_B1LO    (SM_B1HI + 16384)
#define SMEM_BYTES (SM_B1LO + 16384)

template <int MODE>
__global__ __launch_bounds__(256, 1) __cluster_dims__(1, 1, 1)
void tc_gemm(const bf16* __restrict__ Ahi, const bf16* __restrict__ Alo,
             const bf16* __restrict__ Whi, const bf16* __restrict__ Wlo,
             const float* __restrict__ Ball,
             bf16* __restrict__ Chi, bf16* __restrict__ Clo,
             float* __restrict__ Out,
             int K, int N) {
    int rt = blockIdx.x;
    int e  = d_tileExpert[rt];
    if (e < 0) return;
    int rowBase = d_tileRowBase[rt];
    int NTCONV  = N >> 7;                     // conversion layout n-tiles (128 wide)
    int nBase   = blockIdx.y * 256;
    int KC      = K >> 6;
    int tid     = threadIdx.x;
    int nt0     = blockIdx.y * 2;
    size_t wTile0 = ((size_t)(e * NTCONV + nt0)     * KC) * 16384;
    size_t wTile1 = ((size_t)(e * NTCONV + nt0 + 1) * KC) * 16384;

#if HAS_TCGEN05
    extern __shared__ char smem[];
    u32 sb  = smem_u32(smem);
    int wid = tid >> 5, lane = tid & 31;

    if (wid == 0) TC_ALLOC(sb + SM_TMEMPTR, 256);
    if (tid == 0) MBAR_INIT(sb + SM_MBAR, 1);
    __syncthreads();
    u32 tmem;
    asm volatile("ld.shared.b32 %0, [%1];" : "=r"(tmem) : "r"(sb + SM_TMEMPTR));

    const bf16* aH[4];
    const bf16* aL[4];
    u32 aSts[4];
    #pragma unroll
    for (int i = 0; i < 4; i++) {
        int u = tid + 256 * i;
        int r = u >> 3, c = u & 7;
        int grow;
        if (MODE == 0) grow = d_rowtok[rowBase + r];
        else           grow = rowBase + r;
        if (grow >= 0) {
            aH[i] = Ahi + (size_t)grow * K + c * 8;
            aL[i] = Alo + (size_t)grow * K + c * 8;
        } else { aH[i] = 0; aL[i] = 0; }
        aSts[i] = SW128((u32)(r * 128 + c * 16));
    }

    u64 dAh  = MKDESC(sb + SM_AHI);
    u64 dAl  = MKDESC(sb + SM_ALO);
    u64 dB0h = MKDESC(sb + SM_B0HI);
    u64 dB0l = MKDESC(sb + SM_B0LO);
    u64 dB1h = MKDESC(sb + SM_B1HI);
    u64 dB1l = MKDESC(sb + SM_B1LO);

    for (int kc = 0; kc < KC; kc++) {
        if (kc > 0) mbar_wait(sb + SM_MBAR, (kc - 1) & 1);

        // A tiles (hi, lo): gathered rows, swizzled STS.128
        #pragma unroll
        for (int i = 0; i < 4; i++) {
            uint4 vh = aH[i] ? *(const uint4*)(aH[i] + kc * 64)
                             : make_uint4(0, 0, 0, 0);
            uint4 vl = aL[i] ? *(const uint4*)(aL[i] + kc * 64)
                             : make_uint4(0, 0, 0, 0);
            *(uint4*)(smem + SM_AHI + aSts[i]) = vh;
            *(uint4*)(smem + SM_ALO + aSts[i]) = vl;
        }
        // Two B tile pairs: straight copies of pre-swizzled 16KB images
        {
            const char* s0h = (const char*)Whi + wTile0 + (size_t)kc * 16384;
            const char* s0l = (const char*)Wlo + wTile0 + (size_t)kc * 16384;
            const char* s1h = (const char*)Whi + wTile1 + (size_t)kc * 16384;
            const char* s1l = (const char*)Wlo + wTile1 + (size_t)kc * 16384;
            #pragma unroll
            for (int i = 0; i < 4; i++) {
                int o = (tid + 256 * i) * 16;
                *(uint4*)(smem + SM_B0HI + o) = *(const uint4*)(s0h + o);
                *(uint4*)(smem + SM_B0LO + o) = *(const uint4*)(s0l + o);
                *(uint4*)(smem + SM_B1HI + o) = *(const uint4*)(s1h + o);
                *(uint4*)(smem + SM_B1LO + o) = *(const uint4*)(s1l + o);
            }
        }
        FENCE_ASYNC();
        __syncthreads();

        if (wid == 0 && elect_one()) {
            #pragma unroll
            for (int s = 0; s < 4; s++) {
                u32 en0 = (kc == 0 && s == 0) ? 0u : 1u;
                u64 ks = 2 * s;
                mma_f16_ss(tmem,       dAh + ks, dB0h + ks, IDESC_128x128, en0);
                mma_f16_ss(tmem + 128, dAh + ks, dB1h + ks, IDESC_128x128, en0);
                mma_f16_ss(tmem,       dAl + ks, dB0h + ks, IDESC_128x128, 1u);
                mma_f16_ss(tmem + 128, dAl + ks, dB1h + ks, IDESC_128x128, 1u);
                mma_f16_ss(tmem,       dAh + ks, dB0l + ks, IDESC_128x128, 1u);
                mma_f16_ss(tmem + 128, dAh + ks, dB1l + ks, IDESC_128x128, 1u);
            }
            TC_COMMIT(sb + SM_MBAR);
        }
    }

    mbar_wait(sb + SM_MBAR, (KC - 1) & 1);
    TC_FENCE_AFTER();

    // Epilogue: warps 0-3 only (TMEM D = 128 lanes = 4 subpartitions).
    if (wid < 4) {
        int pr = rowBase + wid * 32 + lane;

        if (MODE == 2) {
            int tok  = d_rowtok[pr];
            float gt = d_rowgate[pr];
            #pragma unroll
            for (int nt = 0; nt < 2; nt++) {
                const float* bias = Ball + (size_t)e * N + nBase + nt * 128;
                float* orow = (tok >= 0)
                            ? (Out + (size_t)tok * N + nBase + nt * 128) : 0;
                #pragma unroll
                for (int cb = 0; cb < 128; cb += 32) {
                    u32 dreg[32];
                    TC_LD_X32(dreg, tmem + nt * 128 + cb);
                    TC_WAIT_LD();
                    if (orow) {
                        #pragma unroll
                        for (int c = 0; c < 32; c++) {
                            float v = __uint_as_float(dreg[c]) + __ldg(bias + cb + c);
                            atomicAdd(orow + cb + c, gt * v);
                        }
                    }
                }
            }
        } else {
            #pragma unroll
            for (int nt = 0; nt < 2; nt++) {
                const float* bias = Ball + (size_t)e * N + nBase + nt * 128;
                size_t rowoff = (size_t)pr * N + nBase + nt * 128;
                #pragma unroll
                for (int cb = 0; cb < 128; cb += 32) {
                    u32 dreg[32];
                    TC_LD_X32(dreg, tmem + nt * 128 + cb);
                    TC_WAIT_LD();
                    #pragma unroll
                    for (int g = 0; g < 4; g++) {
                        u32 hp[4], lp[4];
                        #pragma unroll
                        for (int j = 0; j < 4; j++) {
                            int c0 = g * 8 + 2 * j;
                            float v0 = __uint_as_float(dreg[c0])     + __ldg(bias + cb + c0);
                            float v1 = __uint_as_float(dreg[c0 + 1]) + __ldg(bias + cb + c0 + 1);
                            v0 = fmaxf(v0, 0.0f);
                            v1 = fmaxf(v1, 0.0f);
                            bf16 h0 = __float2bfloat16(v0);
                            bf16 h1 = __float2bfloat16(v1);
                            bf16 l0 = __float2bfloat16(v0 - __bfloat162float(h0));
                            bf16 l1 = __float2bfloat16(v1 - __bfloat162float(h1));
                            hp[j] = ((u32)__bfloat16_as_ushort(h1) << 16) | __bfloat16_as_ushort(h0);
                            lp[j] = ((u32)__bfloat16_as_ushort(l1) << 16) | __bfloat16_as_ushort(l0);
                        }
                        *(uint4*)(Chi + rowoff + cb + g * 8) = make_uint4(hp[0], hp[1], hp[2], hp[3]);
                        *(uint4*)(Clo + rowoff + cb + g * 8) = make_uint4(lp[0], lp[1], lp[2], lp[3]);
                    }
                }
            }
        }
        TC_FENCE_BEFORE();
    }

    __syncthreads();
    if (tid == 0) MBAR_INVAL(sb + SM_MBAR);
    __syncthreads();
    if (wid == 0) TC_DEALLOC(tmem, 256);

#else
    // -------- scalar fallback (plain sm_103 pass; never runs on GB300) ------
    int tx = tid & 15, ty = tid >> 4;
    int mSub = ty * 8, nSub = tx * 8;

    const bf16 *ah[8], *al[8];
    #pragma unroll
    for (int i = 0; i < 8; i++) {
        int r = mSub + i;
        int grow;
        if (MODE == 0) grow = d_rowtok[rowBase + r];
        else           grow = rowBase + r;
        if (grow >= 0) {
            ah[i] = Ahi + (size_t)grow * K;
            al[i] = Alo + (size_t)grow * K;
        } else { ah[i] = 0; al[i] = 0; }
    }

    for (int half = 0; half < 2; half++) {
        size_t wTile = (half == 0) ? wTile0 : wTile1;
        int nB = nBase + half * 128;

        float acc[8][8];
        #pragma unroll
        for (int i = 0; i < 8; i++)
            #pragma unroll
            for (int j = 0; j < 8; j++) acc[i][j] = 0.0f;

        for (int k = 0; k < K; k++) {
            int kc = k >> 6, kk = k & 63;
            const char* bH = (const char*)Whi + wTile + (size_t)kc * 16384;
            const char* bL = (const char*)Wlo + wTile + (size_t)kc * 16384;
            float bv[8];
            #pragma unroll
            for (int j = 0; j < 8; j++) {
                int n = nSub + j;
                u32 off = SW128((u32)(n * 128 + (kk >> 3) * 16)) + (kk & 7) * 2;
                bv[j] = __bfloat162float(*(const bf16*)(bH + off)) +
                        __bfloat162float(*(const bf16*)(bL + off));
            }
            #pragma unroll
            for (int i = 0; i < 8; i++) {
                float a = ah[i] ? (__bfloat162float(__ldg(ah[i] + k)) +
                                   __bfloat162float(__ldg(al[i] + k))) : 0.0f;
                #pragma unroll
                for (int j = 0; j < 8; j++) acc[i][j] = fmaf(a, bv[j], acc[i][j]);
            }
        }

        const float* bias = Ball + (size_t)e * N + nB;
        if (MODE == 2) {
            #pragma unroll
            for (int i = 0; i < 8; i++) {
                int pr  = rowBase + mSub + i;
                int tok = d_rowtok[pr];
                if (tok < 0) continue;
                float g = d_rowgate[pr];
                float* orow = Out + (size_t)tok * N + nB;
                #pragma unroll
                for (int j = 0; j < 8; j++)
                    atomicAdd(orow + nSub + j, g * (acc[i][j] + bias[nSub + j]));
            }
        } else {
            #pragma unroll
            for (int i = 0; i < 8; i++) {
                size_t rowoff = (size_t)(rowBase + mSub + i) * N + nB;
                #pragma unroll
                for (int j = 0; j < 8; j++) {
                    float v = fmaxf(acc[i][j] + bias[nSub + j], 0.0f);
                    bf16 h = __float2bfloat16(v);
                    bf16 l = __float2bfloat16(v - __bfloat162float(h));
                    Chi[rowoff + nSub + j] = h;
                    Clo[rowoff + nSub + j] = l;
                }
            }
        }
    }
#endif
}

// ---------------- launch -----------------------------------------------------
extern "C" void kernel_launch(void* const* d_in, const int* in_sizes, int n_in,
                              void* d_out, int out_size) {
    const float* x  = (const float*)d_in[0];
    const float* Wr = (const float*)d_in[1];
    const float* br = (const float*)d_in[2];
    const float* W1 = (const float*)d_in[3];
    const float* b1 = (const float*)d_in[4];
    const float* W2 = (const float*)d_in[5];
    const float* b2 = (const float*)d_in[6];
    const float* W3 = (const float*)d_in[7];
    const float* b3 = (const float*)d_in[8];
    float* out = (float*)d_out;

    bf16 *xhi, *xlo, *w1h, *w1l, *w2h, *w2l, *w3h, *w3l, *h1h, *h1l, *h2h, *h2l;
    cudaGetSymbolAddress((void**)&xhi, g_xhi);
    cudaGetSymbolAddress((void**)&xlo, g_xlo);
    cudaGetSymbolAddress((void**)&w1h, g_w1hi);
    cudaGetSymbolAddress((void**)&w1l, g_w1lo);
    cudaGetSymbolAddress((void**)&w2h, g_w2hi);
    cudaGetSymbolAddress((void**)&w2l, g_w2lo);
    cudaGetSymbolAddress((void**)&w3h, g_w3hi);
    cudaGetSymbolAddress((void**)&w3l, g_w3lo);
    cudaGetSymbolAddress((void**)&h1h, g_h1hi);
    cudaGetSymbolAddress((void**)&h1l, g_h1lo);
    cudaGetSymbolAddress((void**)&h2h, g_h2hi);
    cudaGetSymbolAddress((void**)&h2l, g_h2lo);

    cudaFuncSetAttribute(tc_gemm<0>, cudaFuncAttributeMaxDynamicSharedMemorySize, SMEM_BYTES);
    cudaFuncSetAttribute(tc_gemm<1>, cudaFuncAttributeMaxDynamicSharedMemorySize, SMEM_BYTES);
    cudaFuncSetAttribute(tc_gemm<2>, cudaFuncAttributeMaxDynamicSharedMemorySize, SMEM_BYTES);

    // Lazy one-time stream/event setup (host-side handles only; no device mem).
    // Created on the first (non-captured) correctness call; reused thereafter.
    static cudaStream_t sW = 0;
    static cudaEvent_t evFork = 0, evW1 = 0, evW2 = 0, evW3 = 0;
    if (sW == 0) {
        cudaStreamCreateWithFlags(&sW, cudaStreamNonBlocking);
        cudaEventCreateWithFlags(&evFork, cudaEventDisableTiming);
        cudaEventCreateWithFlags(&evW1,   cudaEventDisableTiming);
        cudaEventCreateWithFlags(&evW2,   cudaEventDisableTiming);
        cudaEventCreateWithFlags(&evW3,   cudaEventDisableTiming);
    }

    // Fork: weight conversions run on side stream, overlapping router + gemm1/2.
    cudaEventRecord(evFork, 0);
    cudaStreamWaitEvent(sW, evFork, 0);
    convert_w_kernel<<<dim3(D_DIM / 64, H_DIM / 128, E_NUM), 256, 0, sW>>>(
        W1, w1h, w1l, D_DIM, H_DIM);
    cudaEventRecord(evW1, sW);
    convert_w_kernel<<<dim3(H_DIM / 64, H_DIM / 128, E_NUM), 256, 0, sW>>>(
        W2, w2h, w2l, H_DIM, H_DIM);
    cudaEventRecord(evW2, sW);
    convert_w_kernel<<<dim3(H_DIM / 64, O_DIM / 128, E_NUM), 256, 0, sW>>>(
        W3, w3h, w3l, H_DIM, O_DIM);
    cudaEventRecord(evW3, sW);

    // Main stream: routing chain + activation conversion.
    init_kernel<<<12, 256>>>();
    router_kernel<<<B_TOK, 256>>>(x, Wr, br);
    scan_kernel<<<1, 32>>>();
    scatter_kernel<<<MAXPAIR / 256, 256>>>();
    cudaMemsetAsync(out, 0, (size_t)B_TOK * O_DIM * sizeof(float), 0);
    convert_x_kernel<<<B_TOK * D_DIM / 1024, 256>>>(x, xhi, xlo);

    cudaStreamWaitEvent(0, evW1, 0);
    tc_gemm<0><<<dim3(MAXTILES, H_DIM / 256), 256, SMEM_BYTES>>>(
        xhi, xlo, w1h, w1l, b1, h1h, h1l, 0, D_DIM, H_DIM);
    cudaStreamWaitEvent(0, evW2, 0);
    tc_gemm<1><<<dim3(MAXTILES, H_DIM / 256), 256, SMEM_BYTES>>>(
        h1h, h1l, w2h, w2l, b2, h2h, h2l, 0, H_DIM, H_DIM);
    cudaStreamWaitEvent(0, evW3, 0);
    tc_gemm<2><<<dim3(MAXTILES, O_DIM / 256), 256, SMEM_BYTES>>>(
        h2h, h2l, w3h, w3l, b3, 0, 0, out, H_DIM, O_DIM);
}